// round 8
// baseline (speedup 1.0000x reference)
#include <cuda_runtime.h>
#include <cstdint>
#include <cstddef>

#define BB 512
#define NT 512
#define NW 16
#define TJ 16    // j per tile (16 warps x 1 row)
#define TK 128   // k per tile
#define TI 16    // i per tile
#define GR 4     // rows per group
#define NGRP (TI / GR)
#define NTILE 4096   // (512/16 j) * (512/128 k) * (512/16 i)
#define GRID 296
#define STAGE_ULL (GR * NW * TK)              // 8192 ull = 64 KB
#define SMEM_BYTES (2048 + STAGE_ULL * 8)     // 67584

// Face accumulators: {exp-sum, masked-x-sum}; .bss => zero at load,
// finalize_kernel re-zeroes after consuming, so every launch sees zeros.
__device__ float2 gF0[BB * BB];  // [j*B+k]: sum over i
__device__ float2 gF1[BB * BB];  // [i*B+k]: sum over j
__device__ float2 gF2[BB * BB];  // [i*B+j]: sum over k

__device__ __forceinline__ void redAdd2(float2* p, float a, float b) {
    asm volatile("red.global.add.v2.f32 [%0], {%1, %2};"
                 :: "l"(p), "f"(a), "f"(b));
}
__device__ __forceinline__ unsigned long long pk2(float lo, float hi) {
    unsigned long long r;
    asm("mov.b64 %0, {%1, %2};" : "=l"(r) : "f"(lo), "f"(hi));
    return r;
}
__device__ __forceinline__ void fadd2(unsigned long long& a, unsigned long long b) {
    asm("add.rn.f32x2 %0, %0, %1;" : "+l"(a) : "l"(b));
}
__device__ __forceinline__ float lo2(unsigned long long a) {
    float f; asm("{.reg .f32 h; mov.b64 {%0, h}, %1;}" : "=f"(f) : "l"(a)); return f;
}
__device__ __forceinline__ float hi2(unsigned long long a) {
    float f; asm("{.reg .f32 l; mov.b64 {l, %0}, %1;}" : "=f"(f) : "l"(a)); return f;
}

__device__ __forceinline__ size_t tile_off(int t, int w, int lane) {
    int it = t >> 7;          // i-split (0..31)
    int rem = t & 127;
    int jt = rem >> 2;        // j tile (0..31)
    int kt = rem & 3;         // k tile (0..3)
    return ((size_t)(it * TI) << 18)
         + ((size_t)(jt * TJ + w) << 9)
         + (size_t)(kt * TK + lane * 4);
}

__global__ __launch_bounds__(NT, 2) void main_kernel(const float* __restrict__ x,
                                                     const float* __restrict__ target,
                                                     float* __restrict__ out) {
    const int tid  = threadIdx.x;
    const int lane = tid & 31;
    const int w    = tid >> 5;
    const unsigned FULL = 0xffffffffu;

    extern __shared__ char smem[];
    int* scls = reinterpret_cast<int*>(smem);
    unsigned long long* sF1 = reinterpret_cast<unsigned long long*>(smem + 2048);

    // classes computed locally (round(t) >= 0 <=> t >= -0.5, round-half-even)
    scls[tid] = (target[tid] >= -0.5f) ? 1 : 0;
    if (blockIdx.x == 0 && tid == 0) out[0] = 0.f;  // reset before finalize adds
    __syncthreads();

    for (int t = blockIdx.x; t < NTILE; t += GRID) {
        const int rem = t & 127;
        const int j   = (rem >> 2) * TJ + w;
        const int k0  = (rem & 3) * TK;
        const int i0  = (t >> 7) * TI;
        const int kk  = k0 + lane * 4;

        const int cj = scls[j];
        const float w1q0 = (float)scls[kk];
        const float w1q1 = (float)scls[kk + 1];
        const float w1q2 = (float)scls[kk + 2];
        const float w1q3 = (float)scls[kk + 3];

        unsigned long long a0[4] = {0ull, 0ull, 0ull, 0ull};  // F0 {E,S} packed

        const float* p = x + ((size_t)i0 << 18) + ((size_t)j << 9) + kk;
        float4 v[GR];
#pragma unroll
        for (int r = 0; r < GR; r++)
            v[r] = *reinterpret_cast<const float4*>(p + ((size_t)r << 18));

        for (int g = 0; g < NGRP; g++) {
            // depth-4 prefetch: entire next group (or next tile's first group)
            const float* pn;
            if (g + 1 < NGRP) pn = p + ((size_t)GR << 18);
            else {
                int tn = t + GRID;
                pn = (tn < NTILE) ? (x + tile_off(tn, w, lane)) : p;
            }
            float4 n[GR];
#pragma unroll
            for (int r = 0; r < GR; r++)
                n[r] = *reinterpret_cast<const float4*>(pn + ((size_t)r << 18));

            const int ib = i0 + g * GR;
            float vv[8];  // vv[0..3]=E per row, vv[4..7]=S per row

#pragma unroll
            for (int r = 0; r < GR; r++) {
                const int ci = scls[ib + r];
                const float fij = (cj == ci) ? 1.f : 0.f;
                const float4 q = v[r];
                float e0 = __expf(q.x), e1 = __expf(q.y);
                float e2 = __expf(q.z), e3 = __expf(q.w);
                float sv  = (q.x + q.y) + (q.z + q.w);
                float rs1 = q.x * w1q0 + q.y * w1q1 + q.z * w1q2 + q.w * w1q3;
                vv[4 + r] = ci ? rs1 : (sv - rs1);
                vv[r]     = (e0 + e1) + (e2 + e3);
                unsigned long long t0 = pk2(e0, fij * q.x);
                unsigned long long t1 = pk2(e1, fij * q.y);
                unsigned long long t2 = pk2(e2, fij * q.z);
                unsigned long long t3 = pk2(e3, fij * q.w);
                fadd2(a0[0], t0); fadd2(a0[1], t1);
                fadd2(a0[2], t2); fadd2(a0[3], t3);
                ulonglong2* d = reinterpret_cast<ulonglong2*>(
                    sF1 + ((size_t)r * NW + w) * TK + lane * 4);
                d[0] = make_ulonglong2(t0, t1);
                d[1] = make_ulonglong2(t2, t3);
            }

            // batched F2 reduction: 8 values x 32 lanes in 9 SHFL
            {
                bool hi16 = (lane & 16) != 0;
#pragma unroll
                for (int r = 0; r < 4; r++) {
                    float send = hi16 ? vv[r] : vv[4 + r];
                    float keep = hi16 ? vv[4 + r] : vv[r];
                    vv[r] = keep + __shfl_xor_sync(FULL, send, 16);
                }
                bool hi8 = (lane & 8) != 0;
                {
                    float s0 = hi8 ? vv[0] : vv[2];
                    float k0v = hi8 ? vv[2] : vv[0];
                    vv[0] = k0v + __shfl_xor_sync(FULL, s0, 8);
                    float s1 = hi8 ? vv[1] : vv[3];
                    float k1v = hi8 ? vv[3] : vv[1];
                    vv[1] = k1v + __shfl_xor_sync(FULL, s1, 8);
                }
                bool hi4 = (lane & 4) != 0;
                {
                    float s0 = hi4 ? vv[0] : vv[1];
                    float k0v = hi4 ? vv[1] : vv[0];
                    vv[0] = k0v + __shfl_xor_sync(FULL, s0, 4);
                }
                vv[0] += __shfl_xor_sync(FULL, vv[0], 2);
                vv[0] += __shfl_xor_sync(FULL, vv[0], 1);
                if ((lane & 3) == 0) {
                    int r  = ((lane >> 3) & 1) * 2 + ((lane >> 2) & 1);
                    int es = (lane >> 4) & 1;
                    atomicAdd(reinterpret_cast<float*>(gF2)
                                  + (((size_t)(ib + r) << 9) + j) * 2 + es,
                              vv[0]);
                }
            }

            __syncthreads();
            {   // F1 gather: all 512 threads, one (row,k) slot each
                const int row = tid >> 7;
                const int kx  = tid & (TK - 1);
                const unsigned long long* gp = sF1 + (size_t)row * (NW * TK) + kx;
                unsigned long long s = gp[0];
#pragma unroll
                for (int ww = 1; ww < NW; ww++) fadd2(s, gp[(size_t)ww * TK]);
                redAdd2(&gF1[((size_t)(ib + row) << 9) + k0 + kx], lo2(s), hi2(s));
            }
            __syncthreads();

#pragma unroll
            for (int r = 0; r < GR; r++) v[r] = n[r];
            p = pn;
        }

        // flush F0 for this (j, k-quad) over the tile's 16 i
#pragma unroll
        for (int q = 0; q < 4; q++)
            redAdd2(&gF0[((size_t)j << 9) + kk + q], lo2(a0[q]), hi2(a0[q]));
    }
}

__global__ void finalize_kernel(const float* __restrict__ target,
                                float* __restrict__ out) {
    const int tidx = threadIdx.x;                 // 512 threads
    const int t = blockIdx.x * 512 + tidx;        // B*B slots, a = blockIdx.x
    const int cb = (target[tidx] >= -0.5f) ? 1 : 0;
    const int n1 = __syncthreads_count(cb);
    const int ca = (target[blockIdx.x] >= -0.5f) ? 1 : 0;

    float2 f0 = gF0[t], f1 = gF1[t], f2 = gF2[t];
    float2 z = make_float2(0.f, 0.f);
    gF0[t] = z; gF1[t] = z; gF2[t] = z;   // self-zero for next launch

    float c = 0.f;
    if (ca == cb) {
        float n = (float)(ca ? n1 : (BB - n1));
        c = __logf(f0.x) + __logf(f1.x) + __logf(f2.x)
            - (f0.y + f1.y + f2.y) * (1.0f / n);
    }
    c *= (1.0f / (float)(BB * BB));
#pragma unroll
    for (int o = 16; o > 0; o >>= 1) c += __shfl_xor_sync(0xffffffffu, c, o);
    __shared__ float sacc[16];
    if ((tidx & 31) == 0) sacc[tidx >> 5] = c;
    __syncthreads();
    if (tidx < 16) {
        float vsum = sacc[tidx];
#pragma unroll
        for (int o = 8; o > 0; o >>= 1) vsum += __shfl_xor_sync(0xffffu, vsum, o);
        if (tidx == 0) atomicAdd(out, vsum);
    }
}

extern "C" void kernel_launch(void* const* d_in, const int* in_sizes, int n_in,
                              void* d_out, int out_size) {
    const float* cube   = (const float*)d_in[0];
    const float* target = (const float*)d_in[1];
    if (n_in >= 2 && in_sizes[0] < in_sizes[1]) {  // defensive order check
        cube   = (const float*)d_in[1];
        target = (const float*)d_in[0];
    }
    float* out = (float*)d_out;

    static bool attr_set = false;
    if (!attr_set) {
        cudaFuncSetAttribute(main_kernel,
                             cudaFuncAttributeMaxDynamicSharedMemorySize, SMEM_BYTES);
        attr_set = true;
    }

    main_kernel<<<GRID, NT, SMEM_BYTES>>>(cube, target, out);
    finalize_kernel<<<BB * BB / 512, 512>>>(target, out);
}

// round 9
// speedup vs baseline: 1.1118x; 1.1118x over previous
#include <cuda_runtime.h>
#include <cstdint>
#include <cstddef>

#define BB 512
#define NT 256
#define GRID 296
#define NTILE 8192   // 64 j-tiles (8 j each) x 128 i-splits (4 i each)
#define SMEM_BYTES (2048 + 2 * 4096 * 8)  // scls + double-buffered F1 staging

typedef unsigned long long ull;

// Face accumulators {E,S} as float2 pairs; .bss zero at load, finalize re-zeroes.
__device__ float4 gF0[BB * BB / 2];  // [j*B+k]: sum over i
__device__ float4 gF1[BB * BB / 2];  // [i*B+k]: sum over j
__device__ float4 gF2[BB * BB / 2];  // [i*B+j]: sum over k

__device__ __forceinline__ void redAdd2(float2* p, float a, float b) {
    asm volatile("red.global.add.v2.f32 [%0], {%1, %2};"
                 :: "l"(p), "f"(a), "f"(b));
}
__device__ __forceinline__ ull pk2(float lo, float hi) {
    ull r; asm("mov.b64 %0, {%1, %2};" : "=l"(r) : "f"(lo), "f"(hi)); return r;
}
__device__ __forceinline__ void fadd2(ull& a, ull b) {
    asm("add.rn.f32x2 %0, %0, %1;" : "+l"(a) : "l"(b));
}
__device__ __forceinline__ float lo2(ull a) {
    float f; asm("{.reg .f32 h; mov.b64 {%0, h}, %1;}" : "=f"(f) : "l"(a)); return f;
}
__device__ __forceinline__ float hi2(ull a) {
    float f; asm("{.reg .f32 l; mov.b64 {l, %0}, %1;}" : "=f"(f) : "l"(a)); return f;
}

// process one row (i, j): update F0 accum, F1 accum, emit F2 values
#define ROW(vq, cjv, jj) { \
    const float fij = ((cjv) == ci) ? 1.f : 0.f; \
    float e0 = __expf(vq.x), e1 = __expf(vq.y), e2 = __expf(vq.z), e3 = __expf(vq.w); \
    ull t0 = pk2(e0, fij * vq.x), t1 = pk2(e1, fij * vq.y); \
    ull t2 = pk2(e2, fij * vq.z), t3 = pk2(e3, fij * vq.w); \
    fadd2(a0[(jj)*4+0], t0); fadd2(a0[(jj)*4+1], t1); \
    fadd2(a0[(jj)*4+2], t2); fadd2(a0[(jj)*4+3], t3); \
    fadd2(f1q0, t0); fadd2(f1q1, t1); fadd2(f1q2, t2); fadd2(f1q3, t3); \
    float sv  = (vq.x + vq.y) + (vq.z + vq.w); \
    float rs1 = vq.x * w1q0 + vq.y * w1q1 + vq.z * w1q2 + vq.w * w1q3; \
    vv[4 + (jj)] = ci ? rs1 : (sv - rs1); \
    vv[(jj)] = (e0 + e1) + (e2 + e3); }

__global__ __launch_bounds__(NT, 2) void main_kernel(const float* __restrict__ x,
                                                     const float* __restrict__ target,
                                                     float* __restrict__ out) {
    const int tid  = threadIdx.x;
    const int lane = tid & 31;
    const int w    = tid >> 5;       // 0..7
    const int quad = w >> 2;         // 0..1 : which 4-j group
    const int wk   = w & 3;          // 0..3 : k-segment of the 2KB row
    const int kb   = wk * 128 + lane * 4;
    const unsigned FULL = 0xffffffffu;

    extern __shared__ char smem[];
    int* scls = reinterpret_cast<int*>(smem);
    ull* sF1  = reinterpret_cast<ull*>(smem + 2048);

    scls[tid]       = (target[tid] >= -0.5f) ? 1 : 0;
    scls[tid + 256] = (target[tid + 256] >= -0.5f) ? 1 : 0;
    if (blockIdx.x == 0 && tid == 0) out[0] = 0.f;
    __syncthreads();

    const float w1q0 = (float)scls[kb],     w1q1 = (float)scls[kb + 1];
    const float w1q2 = (float)scls[kb + 2], w1q3 = (float)scls[kb + 3];

    const int t0r = (int)((long long)blockIdx.x * NTILE / GRID);
    const int t1r = (int)((long long)(blockIdx.x + 1) * NTILE / GRID);

    ull a0[16];                       // F0 accum: 4 jj x 4 k, chained over i-splits
    int cj0 = 0, cj1 = 0, cj2 = 0, cj3 = 0, jbase = 0, curjt = -1;

    const float* base = x + ((size_t)((t0r & 127) * 4) << 18)
                          + ((size_t)((t0r >> 7) * 8 + quad * 4) << 9) + kb;
    float4 v0 = __ldcs(reinterpret_cast<const float4*>(base));
    float4 v1 = __ldcs(reinterpret_cast<const float4*>(base + 512));
    float4 v2 = __ldcs(reinterpret_cast<const float4*>(base + 1024));
    float4 v3 = __ldcs(reinterpret_cast<const float4*>(base + 1536));

    for (int t = t0r; t < t1r; t++) {
        const int jt = t >> 7;
        if (jt != curjt) {
            if (curjt >= 0) {   // flush F0 for previous j-tile
                float2* f0p = reinterpret_cast<float2*>(gF0);
#pragma unroll
                for (int jj = 0; jj < 4; jj++) {
                    float2* p = f0p + (((size_t)(jbase + jj)) << 9) + kb;
                    redAdd2(p + 0, lo2(a0[jj*4+0]), hi2(a0[jj*4+0]));
                    redAdd2(p + 1, lo2(a0[jj*4+1]), hi2(a0[jj*4+1]));
                    redAdd2(p + 2, lo2(a0[jj*4+2]), hi2(a0[jj*4+2]));
                    redAdd2(p + 3, lo2(a0[jj*4+3]), hi2(a0[jj*4+3]));
                }
            }
#pragma unroll
            for (int q = 0; q < 16; q++) a0[q] = 0ull;
            curjt = jt;
            jbase = jt * 8 + quad * 4;
            cj0 = scls[jbase];     cj1 = scls[jbase + 1];
            cj2 = scls[jbase + 2]; cj3 = scls[jbase + 3];
        }
        const int i0 = (t & 127) * 4;
        ull* sbuf = sF1 + (size_t)(t & 1) * 4096;

#pragma unroll
        for (int il = 0; il < 4; il++) {
            // depth-4 prefetch of next i-row group (or next tile's first)
            const float* pb;
            if (il < 3) pb = base + ((size_t)(il + 1) << 18);
            else {
                const int tn = (t + 1 < t1r) ? (t + 1) : t;
                pb = x + ((size_t)((tn & 127) * 4) << 18)
                       + ((size_t)((tn >> 7) * 8 + quad * 4) << 9) + kb;
            }
            float4 n0 = __ldcs(reinterpret_cast<const float4*>(pb));
            float4 n1 = __ldcs(reinterpret_cast<const float4*>(pb + 512));
            float4 n2 = __ldcs(reinterpret_cast<const float4*>(pb + 1024));
            float4 n3 = __ldcs(reinterpret_cast<const float4*>(pb + 1536));

            const int ci = scls[i0 + il];
            ull f1q0 = 0ull, f1q1 = 0ull, f1q2 = 0ull, f1q3 = 0ull;
            float vv[8];

            ROW(v0, cj0, 0)
            ROW(v1, cj1, 1)
            ROW(v2, cj2, 2)
            ROW(v3, cj3, 3)

            // F2: batched 8-value butterfly (4 j x {E,S}) over this warp's 128 k
            {
                bool hi16 = (lane & 16) != 0;
#pragma unroll
                for (int r = 0; r < 4; r++) {
                    float send = hi16 ? vv[r] : vv[4 + r];
                    float keep = hi16 ? vv[4 + r] : vv[r];
                    vv[r] = keep + __shfl_xor_sync(FULL, send, 16);
                }
                bool hi8 = (lane & 8) != 0;
                {
                    float s0 = hi8 ? vv[0] : vv[2];
                    float k0v = hi8 ? vv[2] : vv[0];
                    vv[0] = k0v + __shfl_xor_sync(FULL, s0, 8);
                    float s1 = hi8 ? vv[1] : vv[3];
                    float k1v = hi8 ? vv[3] : vv[1];
                    vv[1] = k1v + __shfl_xor_sync(FULL, s1, 8);
                }
                bool hi4 = (lane & 4) != 0;
                {
                    float s0 = hi4 ? vv[0] : vv[1];
                    float k0v = hi4 ? vv[1] : vv[0];
                    vv[0] = k0v + __shfl_xor_sync(FULL, s0, 4);
                }
                vv[0] += __shfl_xor_sync(FULL, vv[0], 2);
                vv[0] += __shfl_xor_sync(FULL, vv[0], 1);
                if ((lane & 3) == 0) {
                    int r  = ((lane >> 3) & 1) * 2 + ((lane >> 2) & 1);
                    int es = (lane >> 4) & 1;   // 8 consecutive floats -> 1 sector
                    atomicAdd(reinterpret_cast<float*>(gF2)
                                  + ((((size_t)(i0 + il)) << 9) + jbase + r) * 2 + es,
                              vv[0]);
                }
            }

            // stage F1 (summed over this warp's 4 j), conflict-free [q][k-grp] layout
            {
                ull* s = sbuf + (size_t)(il * 2 + quad) * 512 + wk * 32 + lane;
                s[0]   = f1q0;
                s[128] = f1q1;
                s[256] = f1q2;
                s[384] = f1q3;
            }

            v0 = n0; v1 = n1; v2 = n2; v3 = n3;
            if (il == 3) base = pb;
        }

        __syncthreads();
        // F1 gather: 512 (il,k4) groups over 256 threads; conflict-free LDS.64
#pragma unroll
        for (int g = 0; g < 2; g++) {
            const int gi = tid + g * 256;
            const int il = gi >> 7;
            const int k4 = (gi & 127) * 4;
            const ull* s0p = sbuf + (size_t)(il * 2 + 0) * 512
                                  + (k4 >> 7) * 32 + ((k4 & 127) >> 2);
            const ull* s1p = s0p + 512;
            ull s0 = s0p[0],   s1 = s0p[128], s2 = s0p[256], s3 = s0p[384];
            fadd2(s0, s1p[0]);   fadd2(s1, s1p[128]);
            fadd2(s2, s1p[256]); fadd2(s3, s1p[384]);
            float2* p = reinterpret_cast<float2*>(gF1) + (((size_t)(i0 + il)) << 9) + k4;
            redAdd2(p + 0, lo2(s0), hi2(s0));
            redAdd2(p + 1, lo2(s1), hi2(s1));
            redAdd2(p + 2, lo2(s2), hi2(s2));
            redAdd2(p + 3, lo2(s3), hi2(s3));
        }
    }

    // final F0 flush
    {
        float2* f0p = reinterpret_cast<float2*>(gF0);
#pragma unroll
        for (int jj = 0; jj < 4; jj++) {
            float2* p = f0p + (((size_t)(jbase + jj)) << 9) + kb;
            redAdd2(p + 0, lo2(a0[jj*4+0]), hi2(a0[jj*4+0]));
            redAdd2(p + 1, lo2(a0[jj*4+1]), hi2(a0[jj*4+1]));
            redAdd2(p + 2, lo2(a0[jj*4+2]), hi2(a0[jj*4+2]));
            redAdd2(p + 3, lo2(a0[jj*4+3]), hi2(a0[jj*4+3]));
        }
    }
}

__global__ void finalize_kernel(const float* __restrict__ target,
                                float* __restrict__ out) {
    const int tidx = threadIdx.x;                 // 512 threads
    const int t = blockIdx.x * 512 + tidx;        // B*B slots, a = blockIdx.x
    const int cb = (target[tidx] >= -0.5f) ? 1 : 0;
    const int n1 = __syncthreads_count(cb);
    const int ca = (target[blockIdx.x] >= -0.5f) ? 1 : 0;

    float2* F0 = reinterpret_cast<float2*>(gF0);
    float2* F1 = reinterpret_cast<float2*>(gF1);
    float2* F2 = reinterpret_cast<float2*>(gF2);
    float2 f0 = F0[t], f1 = F1[t], f2 = F2[t];
    float2 z = make_float2(0.f, 0.f);
    F0[t] = z; F1[t] = z; F2[t] = z;   // self-zero for next launch

    float c = 0.f;
    if (ca == cb) {
        float n = (float)(ca ? n1 : (BB - n1));
        c = __logf(f0.x) + __logf(f1.x) + __logf(f2.x)
            - (f0.y + f1.y + f2.y) * (1.0f / n);
    }
    c *= (1.0f / (float)(BB * BB));
#pragma unroll
    for (int o = 16; o > 0; o >>= 1) c += __shfl_xor_sync(0xffffffffu, c, o);
    __shared__ float sacc[16];
    if ((tidx & 31) == 0) sacc[tidx >> 5] = c;
    __syncthreads();
    if (tidx < 16) {
        float vsum = sacc[tidx];
#pragma unroll
        for (int o = 8; o > 0; o >>= 1) vsum += __shfl_xor_sync(0xffffu, vsum, o);
        if (tidx == 0) atomicAdd(out, vsum);
    }
}

extern "C" void kernel_launch(void* const* d_in, const int* in_sizes, int n_in,
                              void* d_out, int out_size) {
    const float* cube   = (const float*)d_in[0];
    const float* target = (const float*)d_in[1];
    if (n_in >= 2 && in_sizes[0] < in_sizes[1]) {  // defensive order check
        cube   = (const float*)d_in[1];
        target = (const float*)d_in[0];
    }
    float* out = (float*)d_out;

    static bool attr_set = false;
    if (!attr_set) {
        cudaFuncSetAttribute(main_kernel,
                             cudaFuncAttributeMaxDynamicSharedMemorySize, SMEM_BYTES);
        attr_set = true;
    }

    main_kernel<<<GRID, NT, SMEM_BYTES>>>(cube, target, out);
    finalize_kernel<<<BB * BB / 512, 512>>>(target, out);
}

// round 10
// speedup vs baseline: 1.5444x; 1.3891x over previous
#include <cuda_runtime.h>
#include <cstdint>
#include <cstddef>

#define BB 512
#define NT 256
#define GRID 456      // 3 blocks/SM x 152 SMs, single wave
#define NTILE 8192    // 64 j-tiles (8 j) x 128 i-splits (4 i)
// smem: [0,2048) classes | [2048, 34816) F1 staging 32KB | [34816, 67584) cp.async pipe 32KB
#define STG_OFF 2048
#define PIPE_OFF 34816
#define SMEM_BYTES 67584

typedef unsigned long long ull;

// Face accumulators {E,S}; .bss zero at load, finalize re-zeroes after reading.
__device__ float4 gF0[BB * BB / 2];  // [j*B+k]: sum over i
__device__ float4 gF1[BB * BB / 2];  // [i*B+k]: sum over j
__device__ float4 gF2[BB * BB / 2];  // [i*B+j]: sum over k

__device__ __forceinline__ void redAdd4(float4* p, float a, float b, float c, float d) {
    asm volatile("red.global.add.v4.f32 [%0], {%1, %2, %3, %4};"
                 :: "l"(p), "f"(a), "f"(b), "f"(c), "f"(d));
}
__device__ __forceinline__ ull pk2(float lo, float hi) {
    ull r; asm("mov.b64 %0, {%1, %2};" : "=l"(r) : "f"(lo), "f"(hi)); return r;
}
__device__ __forceinline__ void fadd2(ull& a, ull b) {
    asm("add.rn.f32x2 %0, %0, %1;" : "+l"(a) : "l"(b));
}
__device__ __forceinline__ float lo2(ull a) {
    float f; asm("{.reg .f32 h; mov.b64 {%0, h}, %1;}" : "=f"(f) : "l"(a)); return f;
}
__device__ __forceinline__ float hi2(ull a) {
    float f; asm("{.reg .f32 l; mov.b64 {l, %0}, %1;}" : "=f"(f) : "l"(a)); return f;
}
__device__ __forceinline__ void cpa16(unsigned dst, const void* src) {
    asm volatile("cp.async.cg.shared.global [%0], [%1], 16;"
                 :: "r"(dst), "l"(src));
}

#define ROW(vq, cjv, jj) { \
    const float fij = ((cjv) == ci) ? 1.f : 0.f; \
    float e0 = __expf(vq.x), e1 = __expf(vq.y), e2 = __expf(vq.z), e3 = __expf(vq.w); \
    ull t0 = pk2(e0, fij * vq.x), t1 = pk2(e1, fij * vq.y); \
    ull t2 = pk2(e2, fij * vq.z), t3 = pk2(e3, fij * vq.w); \
    fadd2(a0[(jj)*4+0], t0); fadd2(a0[(jj)*4+1], t1); \
    fadd2(a0[(jj)*4+2], t2); fadd2(a0[(jj)*4+3], t3); \
    fadd2(f1q0, t0); fadd2(f1q1, t1); fadd2(f1q2, t2); fadd2(f1q3, t3); \
    float sv  = (vq.x + vq.y) + (vq.z + vq.w); \
    float rs1 = vq.x * w1q0 + vq.y * w1q1 + vq.z * w1q2 + vq.w * w1q3; \
    vv[4 + (jj)] = ci ? rs1 : (sv - rs1); \
    vv[(jj)] = (e0 + e1) + (e2 + e3); }

__global__ __launch_bounds__(NT, 3) void main_kernel(const float* __restrict__ x,
                                                     const float* __restrict__ target,
                                                     float* __restrict__ out) {
    const int tid  = threadIdx.x;
    const int lane = tid & 31;
    const int w    = tid >> 5;       // 0..7
    const int quad = w >> 2;         // 0..1
    const int wk   = w & 3;          // 0..3
    const int kb   = wk * 128 + lane * 4;
    const unsigned FULL = 0xffffffffu;

    extern __shared__ char smem[];
    int* scls = reinterpret_cast<int*>(smem);
    ull* sF1  = reinterpret_cast<ull*>(smem + STG_OFF);
    const unsigned pipe_u32 =
        (unsigned)__cvta_generic_to_shared(smem + PIPE_OFF) + tid * 16;

    scls[tid]       = (target[tid] >= -0.5f) ? 1 : 0;
    scls[tid + 256] = (target[tid + 256] >= -0.5f) ? 1 : 0;
    if (blockIdx.x == 0 && tid == 0) out[0] = 0.f;
    __syncthreads();

    const float w1q0 = (float)scls[kb],     w1q1 = (float)scls[kb + 1];
    const float w1q2 = (float)scls[kb + 2], w1q3 = (float)scls[kb + 3];

    const int t0r = (int)((long long)blockIdx.x * NTILE / GRID);
    const int t1r = (int)((long long)(blockIdx.x + 1) * NTILE / GRID);
    const int G   = (t1r - t0r) * 4;   // row-groups (one i each)

    // issue row-group g's 4 cp.async loads into stage (g&1)
#define ISSUE(gi) { \
    int gg = (gi) < G ? (gi) : (G - 1); \
    int tt = t0r + (gg >> 2); \
    int ii = ((tt & 127) << 2) + (gg & 3); \
    int jb = (tt >> 7) * 8 + quad * 4; \
    const float* a = x + ((size_t)ii << 18) + ((size_t)jb << 9) + kb; \
    unsigned d = pipe_u32 + ((gg & 1) << 14); \
    cpa16(d,         a); \
    cpa16(d + 4096,  a + 512); \
    cpa16(d + 8192,  a + 1024); \
    cpa16(d + 12288, a + 1536); \
    asm volatile("cp.async.commit_group;"); }

    ISSUE(0)
    ISSUE(1)

    ull a0[16];
#pragma unroll
    for (int q = 0; q < 16; q++) a0[q] = 0ull;
    int curjt = t0r >> 7;
    int jbase = curjt * 8 + quad * 4;
    int cj0 = scls[jbase],     cj1 = scls[jbase + 1];
    int cj2 = scls[jbase + 2], cj3 = scls[jbase + 3];

    const float4* vpipe = reinterpret_cast<const float4*>(smem + PIPE_OFF) + tid;

    for (int g = 0; g < G; g++) {
        const int tt = t0r + (g >> 2);
        if ((g & 3) == 0) {
            const int jt = tt >> 7;
            if (jt != curjt) {   // flush F0 for finished j-tile
                float4* f0p = reinterpret_cast<float4*>(gF0);
#pragma unroll
                for (int jj = 0; jj < 4; jj++) {
                    float4* p = f0p + ((((size_t)(jbase + jj)) << 9) + kb) / 2;
                    redAdd4(p,     lo2(a0[jj*4+0]), hi2(a0[jj*4+0]),
                                   lo2(a0[jj*4+1]), hi2(a0[jj*4+1]));
                    redAdd4(p + 1, lo2(a0[jj*4+2]), hi2(a0[jj*4+2]),
                                   lo2(a0[jj*4+3]), hi2(a0[jj*4+3]));
                }
#pragma unroll
                for (int q = 0; q < 16; q++) a0[q] = 0ull;
                curjt = jt;
                jbase = jt * 8 + quad * 4;
                cj0 = scls[jbase];     cj1 = scls[jbase + 1];
                cj2 = scls[jbase + 2]; cj3 = scls[jbase + 3];
            }
        }
        const int i  = ((tt & 127) << 2) + (g & 3);
        const int ci = scls[i];

        asm volatile("cp.async.wait_group 1;" ::: "memory");
        const float4* vp = vpipe + ((size_t)(g & 1) << 10);  // stage = 16KB = 1024 float4
        float4 v0 = vp[0];
        float4 v1 = vp[256];
        float4 v2 = vp[512];
        float4 v3 = vp[768];

        ISSUE(g + 2)

        ull f1q0 = 0ull, f1q1 = 0ull, f1q2 = 0ull, f1q3 = 0ull;
        float vv[8];
        ROW(v0, cj0, 0)
        ROW(v1, cj1, 1)
        ROW(v2, cj2, 2)
        ROW(v3, cj3, 3)

        // F2: batched 8-value butterfly (4 j x {E,S}) over this warp's 128 k
        {
            bool hi16 = (lane & 16) != 0;
#pragma unroll
            for (int r = 0; r < 4; r++) {
                float send = hi16 ? vv[r] : vv[4 + r];
                float keep = hi16 ? vv[4 + r] : vv[r];
                vv[r] = keep + __shfl_xor_sync(FULL, send, 16);
            }
            bool hi8 = (lane & 8) != 0;
            {
                float s0 = hi8 ? vv[0] : vv[2];
                float k0v = hi8 ? vv[2] : vv[0];
                vv[0] = k0v + __shfl_xor_sync(FULL, s0, 8);
                float s1 = hi8 ? vv[1] : vv[3];
                float k1v = hi8 ? vv[3] : vv[1];
                vv[1] = k1v + __shfl_xor_sync(FULL, s1, 8);
            }
            bool hi4 = (lane & 4) != 0;
            {
                float s0 = hi4 ? vv[0] : vv[1];
                float k0v = hi4 ? vv[1] : vv[0];
                vv[0] = k0v + __shfl_xor_sync(FULL, s0, 4);
            }
            vv[0] += __shfl_xor_sync(FULL, vv[0], 2);
            vv[0] += __shfl_xor_sync(FULL, vv[0], 1);
            if ((lane & 3) == 0) {
                int r  = ((lane >> 3) & 1) * 2 + ((lane >> 2) & 1);
                int es = (lane >> 4) & 1;
                atomicAdd(reinterpret_cast<float*>(gF2)
                              + ((((size_t)i) << 9) + jbase + r) * 2 + es,
                          vv[0]);
            }
        }

        // stage F1 ({E,S} per k, summed over warp's 4 j); buffer = pair parity
        {
            ull* s = sF1 + (size_t)((g >> 1) & 1) * 2048
                         + (size_t)((g & 1) * 2 + quad) * 512 + wk * 32 + lane;
            s[0]   = f1q0;
            s[128] = f1q1;
            s[256] = f1q2;
            s[384] = f1q3;
        }

        if (g & 1) {   // end of a 2-row pair: gather + red.v4
            __syncthreads();
            const ull* buf = sF1 + (size_t)((g >> 1) & 1) * 2048;
            const int il_p = tid >> 7;
            const int k4   = (tid & 127) * 4;
            const ull* s0p = buf + (size_t)(il_p * 2) * 512
                                 + (k4 >> 7) * 32 + ((k4 >> 2) & 31);
            const ull* s1p = s0p + 512;
            ull s0 = s0p[0],   s1 = s0p[128], s2 = s0p[256], s3 = s0p[384];
            fadd2(s0, s1p[0]);   fadd2(s1, s1p[128]);
            fadd2(s2, s1p[256]); fadd2(s3, s1p[384]);
            const int ig = ((tt & 127) << 2) + (g & 3) - 1 + il_p;
            float4* p = reinterpret_cast<float4*>(gF1)
                        + ((((size_t)ig) << 9) + k4) / 2;
            redAdd4(p,     lo2(s0), hi2(s0), lo2(s1), hi2(s1));
            redAdd4(p + 1, lo2(s2), hi2(s2), lo2(s3), hi2(s3));
        }
    }

    // final F0 flush
    {
        float4* f0p = reinterpret_cast<float4*>(gF0);
#pragma unroll
        for (int jj = 0; jj < 4; jj++) {
            float4* p = f0p + ((((size_t)(jbase + jj)) << 9) + kb) / 2;
            redAdd4(p,     lo2(a0[jj*4+0]), hi2(a0[jj*4+0]),
                           lo2(a0[jj*4+1]), hi2(a0[jj*4+1]));
            redAdd4(p + 1, lo2(a0[jj*4+2]), hi2(a0[jj*4+2]),
                           lo2(a0[jj*4+3]), hi2(a0[jj*4+3]));
        }
    }
}

__global__ void finalize_kernel(const float* __restrict__ target,
                                float* __restrict__ out) {
    const int tidx = threadIdx.x;                 // 512 threads
    const int t = blockIdx.x * 512 + tidx;        // B*B slots, a = blockIdx.x
    const int cb = (target[tidx] >= -0.5f) ? 1 : 0;
    const int n1 = __syncthreads_count(cb);
    const int ca = (target[blockIdx.x] >= -0.5f) ? 1 : 0;

    float2* F0 = reinterpret_cast<float2*>(gF0);
    float2* F1 = reinterpret_cast<float2*>(gF1);
    float2* F2 = reinterpret_cast<float2*>(gF2);
    float2 f0 = F0[t], f1 = F1[t], f2 = F2[t];
    float2 z = make_float2(0.f, 0.f);
    F0[t] = z; F1[t] = z; F2[t] = z;   // self-zero for next launch

    float c = 0.f;
    if (ca == cb) {
        float n = (float)(ca ? n1 : (BB - n1));
        c = __logf(f0.x) + __logf(f1.x) + __logf(f2.x)
            - (f0.y + f1.y + f2.y) * (1.0f / n);
    }
    c *= (1.0f / (float)(BB * BB));
#pragma unroll
    for (int o = 16; o > 0; o >>= 1) c += __shfl_xor_sync(0xffffffffu, c, o);
    __shared__ float sacc[16];
    if ((tidx & 31) == 0) sacc[tidx >> 5] = c;
    __syncthreads();
    if (tidx < 16) {
        float vsum = sacc[tidx];
#pragma unroll
        for (int o = 8; o > 0; o >>= 1) vsum += __shfl_xor_sync(0xffffu, vsum, o);
        if (tidx == 0) atomicAdd(out, vsum);
    }
}

extern "C" void kernel_launch(void* const* d_in, const int* in_sizes, int n_in,
                              void* d_out, int out_size) {
    const float* cube   = (const float*)d_in[0];
    const float* target = (const float*)d_in[1];
    if (n_in >= 2 && in_sizes[0] < in_sizes[1]) {  // defensive order check
        cube   = (const float*)d_in[1];
        target = (const float*)d_in[0];
    }
    float* out = (float*)d_out;

    static bool attr_set = false;
    if (!attr_set) {
        cudaFuncSetAttribute(main_kernel,
                             cudaFuncAttributeMaxDynamicSharedMemorySize, SMEM_BYTES);
        attr_set = true;
    }

    main_kernel<<<GRID, NT, SMEM_BYTES>>>(cube, target, out);
    finalize_kernel<<<BB * BB / 512, 512>>>(target, out);
}